// round 1
// baseline (speedup 1.0000x reference)
#include <cuda_runtime.h>
#include <cuda_bf16.h>

// Problem dims (fixed by the reference)
#define BB 8
#define TT 1024
#define CC 2048
#define MM (BB * TT)          // 8192 rows
#define NELEM (BB * TT * CC)  // 16,777,216

// ---------------------------------------------------------------------------
// Scratch (static device globals; no allocation anywhere)
// ---------------------------------------------------------------------------
__device__ float g_xk[NELEM];
__device__ float g_xv[NELEM];
__device__ float g_xr[NELEM];
__device__ float g_k[NELEM];
__device__ float g_v[NELEM];
__device__ float g_r[NELEM];
__device__ float g_srwkv[NELEM];

// ---------------------------------------------------------------------------
// Kernel 1: time-shift mixing. Produces xk, xv, xr in one pass (float4).
// shifted[b,t,c] = x[b,t-1,c] (0 at t=0);  xk = x*tmk + shifted*(1-tmk), etc.
// ---------------------------------------------------------------------------
__global__ void mix_kernel(const float4* __restrict__ x4,
                           const float4* __restrict__ tmk4,
                           const float4* __restrict__ tmv4,
                           const float4* __restrict__ tmr4,
                           float4* __restrict__ xk4,
                           float4* __restrict__ xv4,
                           float4* __restrict__ xr4) {
    const int C4 = CC / 4;
    int i = blockIdx.x * blockDim.x + threadIdx.x;   // over NELEM/4
    if (i >= NELEM / 4) return;
    int c4 = i % C4;
    int t = (i / C4) % TT;

    float4 xc = x4[i];
    float4 xs = make_float4(0.f, 0.f, 0.f, 0.f);
    if (t > 0) xs = x4[i - C4];

    float4 mk = tmk4[c4], mv = tmv4[c4], mr = tmr4[c4];

    float4 ok, ov, orr;
    ok.x = xc.x * mk.x + xs.x * (1.f - mk.x);
    ok.y = xc.y * mk.y + xs.y * (1.f - mk.y);
    ok.z = xc.z * mk.z + xs.z * (1.f - mk.z);
    ok.w = xc.w * mk.w + xs.w * (1.f - mk.w);
    ov.x = xc.x * mv.x + xs.x * (1.f - mv.x);
    ov.y = xc.y * mv.y + xs.y * (1.f - mv.y);
    ov.z = xc.z * mv.z + xs.z * (1.f - mv.z);
    ov.w = xc.w * mv.w + xs.w * (1.f - mv.w);
    orr.x = xc.x * mr.x + xs.x * (1.f - mr.x);
    orr.y = xc.y * mr.y + xs.y * (1.f - mr.y);
    orr.z = xc.z * mr.z + xs.z * (1.f - mr.z);
    orr.w = xc.w * mr.w + xs.w * (1.f - mr.w);

    xk4[i] = ok;
    xv4[i] = ov;
    xr4[i] = orr;
}

// ---------------------------------------------------------------------------
// Kernel 2: SGEMM, "TN" shape. A:[M,K] row-major, W:[N,K] row-major,
// C[m,n] = sum_k A[m,k]*W[n,k].  128x128 tile, BK=16, 256 threads, 8x8/thread.
// M=8192, N=2048, K=2048 all divide evenly -> no bounds checks.
// ---------------------------------------------------------------------------
#define BM 128
#define BN 128
#define BK 16
#define TM 8
#define TN 8

__global__ __launch_bounds__(256, 2)
void sgemm_tn(const float* __restrict__ A, const float* __restrict__ W,
              float* __restrict__ C, int M, int N, int K) {
    __shared__ float As[BK][BM];
    __shared__ float Bs[BK][BN];

    const int tid = threadIdx.x;          // 0..255
    const int tx = tid & 15;              // 0..15
    const int ty = tid >> 4;              // 0..15
    const int rowBase = blockIdx.y * BM;
    const int colBase = blockIdx.x * BN;

    float acc[TM][TN] = {};
    float a_frag[TM], b_frag[TN];

    for (int k0 = 0; k0 < K; k0 += BK) {
        // Cooperative load: 128 rows x 16 cols each for A and W tiles.
        // 512 float4 per tile, 2 per thread; store transposed to smem.
#pragma unroll
        for (int i = 0; i < 2; i++) {
            int idx = tid + i * 256;
            int row = idx >> 2;       // 0..127
            int cg  = idx & 3;        // 0..3 (group of 4 k's)
            float4 va = *reinterpret_cast<const float4*>(
                &A[(size_t)(rowBase + row) * K + k0 + cg * 4]);
            As[cg * 4 + 0][row] = va.x;
            As[cg * 4 + 1][row] = va.y;
            As[cg * 4 + 2][row] = va.z;
            As[cg * 4 + 3][row] = va.w;
            float4 vb = *reinterpret_cast<const float4*>(
                &W[(size_t)(colBase + row) * K + k0 + cg * 4]);
            Bs[cg * 4 + 0][row] = vb.x;
            Bs[cg * 4 + 1][row] = vb.y;
            Bs[cg * 4 + 2][row] = vb.z;
            Bs[cg * 4 + 3][row] = vb.w;
        }
        __syncthreads();

#pragma unroll
        for (int k = 0; k < BK; k++) {
            *reinterpret_cast<float4*>(&a_frag[0]) =
                *reinterpret_cast<const float4*>(&As[k][ty * TM]);
            *reinterpret_cast<float4*>(&a_frag[4]) =
                *reinterpret_cast<const float4*>(&As[k][ty * TM + 4]);
            *reinterpret_cast<float4*>(&b_frag[0]) =
                *reinterpret_cast<const float4*>(&Bs[k][tx * TN]);
            *reinterpret_cast<float4*>(&b_frag[4]) =
                *reinterpret_cast<const float4*>(&Bs[k][tx * TN + 4]);
#pragma unroll
            for (int i = 0; i < TM; i++)
#pragma unroll
                for (int j = 0; j < TN; j++)
                    acc[i][j] = fmaf(a_frag[i], b_frag[j], acc[i][j]);
        }
        __syncthreads();
    }

    // Epilogue: vectorized stores
#pragma unroll
    for (int i = 0; i < TM; i++) {
        size_t base = (size_t)(rowBase + ty * TM + i) * N + colBase + tx * TN;
        float4 v0 = make_float4(acc[i][0], acc[i][1], acc[i][2], acc[i][3]);
        float4 v1 = make_float4(acc[i][4], acc[i][5], acc[i][6], acc[i][7]);
        *reinterpret_cast<float4*>(&C[base]) = v0;
        *reinterpret_cast<float4*>(&C[base + 4]) = v1;
    }
}

// ---------------------------------------------------------------------------
// Kernel 3: WKV recurrence (numerically stabilized), one thread per (b,c).
// Fuses sigmoid(r) * wkv into the output buffer.
// ---------------------------------------------------------------------------
__global__ void wkv_kernel(const float* __restrict__ k,
                           const float* __restrict__ v,
                           const float* __restrict__ r,
                           const float* __restrict__ time_decay,
                           const float* __restrict__ time_first,
                           float* __restrict__ out) {
    int tidg = blockIdx.x * blockDim.x + threadIdx.x;   // 0 .. B*C-1
    if (tidg >= BB * CC) return;
    int b = tidg / CC;
    int c = tidg % CC;

    const float w = -__expf(time_decay[c]);
    const float u = time_first[c];

    float num = 0.f, den = 0.f, mx = -1e38f;
    size_t base = (size_t)b * TT * CC + c;

#pragma unroll 4
    for (int t = 0; t < TT; t++) {
        size_t idx = base + (size_t)t * CC;
        float kt = k[idx];
        float vt = v[idx];
        float rv = r[idx];

        float ku = kt + u;
        float max_out = fmaxf(mx, ku);
        float e1 = __expf(mx - max_out);
        float e2 = __expf(ku - max_out);
        float o = __fdividef(e1 * num + e2 * vt, e1 * den + e2);

        float mw = mx + w;
        float max_st = fmaxf(mw, kt);
        float e1s = __expf(mw - max_st);
        float e2s = __expf(kt - max_st);
        num = e1s * num + e2s * vt;
        den = e1s * den + e2s;
        mx = max_st;

        float sr = __fdividef(1.f, 1.f + __expf(-rv));
        out[idx] = sr * o;
    }
}

// ---------------------------------------------------------------------------
// Launch
// ---------------------------------------------------------------------------
extern "C" void kernel_launch(void* const* d_in, const int* in_sizes, int n_in,
                              void* d_out, int out_size) {
    const float* x   = (const float*)d_in[0];
    const float* td  = (const float*)d_in[1];
    const float* tf  = (const float*)d_in[2];
    const float* tmk = (const float*)d_in[3];
    const float* tmv = (const float*)d_in[4];
    const float* tmr = (const float*)d_in[5];
    const float* Wk  = (const float*)d_in[6];
    const float* Wv  = (const float*)d_in[7];
    const float* Wr  = (const float*)d_in[8];
    const float* Wo  = (const float*)d_in[9];
    float* out = (float*)d_out;

    static float *p_xk = nullptr, *p_xv = nullptr, *p_xr = nullptr;
    static float *p_k = nullptr, *p_v = nullptr, *p_r = nullptr, *p_s = nullptr;
    if (!p_xk) {
        cudaGetSymbolAddress((void**)&p_xk, g_xk);
        cudaGetSymbolAddress((void**)&p_xv, g_xv);
        cudaGetSymbolAddress((void**)&p_xr, g_xr);
        cudaGetSymbolAddress((void**)&p_k,  g_k);
        cudaGetSymbolAddress((void**)&p_v,  g_v);
        cudaGetSymbolAddress((void**)&p_r,  g_r);
        cudaGetSymbolAddress((void**)&p_s,  g_srwkv);
    }

    // 1. time-shift mixing
    {
        int n4 = NELEM / 4;
        int threads = 256;
        int blocks = (n4 + threads - 1) / threads;
        mix_kernel<<<blocks, threads>>>(
            (const float4*)x, (const float4*)tmk, (const float4*)tmv,
            (const float4*)tmr, (float4*)p_xk, (float4*)p_xv, (float4*)p_xr);
    }

    // 2. three projection GEMMs: [8192,2048] x [2048,2048]^T
    {
        dim3 grid(CC / BN, MM / BM);   // (16, 64)
        sgemm_tn<<<grid, 256>>>(p_xk, Wk, p_k, MM, CC, CC);
        sgemm_tn<<<grid, 256>>>(p_xv, Wv, p_v, MM, CC, CC);
        sgemm_tn<<<grid, 256>>>(p_xr, Wr, p_r, MM, CC, CC);
    }

    // 3. WKV recurrence + sigmoid(r) fusion
    {
        int threads = 128;
        int blocks = (BB * CC + threads - 1) / threads;   // 128
        wkv_kernel<<<blocks, threads>>>(p_k, p_v, p_r, td, tf, p_s);
    }

    // 4. output GEMM into d_out
    {
        dim3 grid(CC / BN, MM / BM);
        sgemm_tn<<<grid, 256>>>(p_s, Wo, out, MM, CC, CC);
    }
}

// round 3
// speedup vs baseline: 2.6259x; 2.6259x over previous
#include <cuda_runtime.h>
#include <cuda_bf16.h>
#include <cstdint>

// Problem dims
#define BB 8
#define TT 1024
#define CC 2048
#define MM (BB * TT)          // 8192
#define NELEM (BB * TT * CC)  // 16,777,216

// GEMM tiling (HMMA mma.sync path)
#define BM 128
#define BN 128
#define BKK 32
#define NITER (CC / BKK)      // 64
#define SROWB 80              // padded row stride in bytes (40 bf16)
#define TILEB (128 * SROWB)   // 10240 bytes per tile
#define STAGEB (4 * TILEB)    // Ah, Al, Bh, Bl
#define GSMEM (2 * STAGEB)    // 81920 bytes

// ---------------------------------------------------------------------------
// Scratch (static device globals; no allocation anywhere)
// ---------------------------------------------------------------------------
__device__ __nv_bfloat16 g_xkh[NELEM], g_xkl[NELEM];
__device__ __nv_bfloat16 g_xvh[NELEM], g_xvl[NELEM];
__device__ __nv_bfloat16 g_xrh[NELEM], g_xrl[NELEM];
__device__ __nv_bfloat16 g_wh[4ULL * CC * CC], g_wl[4ULL * CC * CC];
__device__ float g_k[NELEM], g_v[NELEM], g_r[NELEM];
__device__ __nv_bfloat16 g_sh[NELEM], g_sl[NELEM];

// ---------------------------------------------------------------------------
// Helpers
// ---------------------------------------------------------------------------
__device__ __forceinline__ uint32_t smem_u32(const void* p) {
    uint32_t a;
    asm("{ .reg .u64 t; cvta.to.shared.u64 t, %1; cvt.u32.u64 %0, t; }"
        : "=r"(a) : "l"(p));
    return a;
}

__device__ __forceinline__ void cp_async16(uint32_t saddr, const void* gaddr) {
    asm volatile("cp.async.cg.shared.global [%0], [%1], 16;"
                 :: "r"(saddr), "l"(gaddr));
}
__device__ __forceinline__ void cp_commit() {
    asm volatile("cp.async.commit_group;");
}
__device__ __forceinline__ void cp_wait1() {
    asm volatile("cp.async.wait_group 1;");
}
__device__ __forceinline__ void cp_wait0() {
    asm volatile("cp.async.wait_group 0;");
}

__device__ __forceinline__ void ldsm_x4(uint32_t addr, uint32_t& r0, uint32_t& r1,
                                        uint32_t& r2, uint32_t& r3) {
    asm volatile("ldmatrix.sync.aligned.m8n8.x4.shared.b16 {%0,%1,%2,%3}, [%4];"
                 : "=r"(r0), "=r"(r1), "=r"(r2), "=r"(r3) : "r"(addr));
}

__device__ __forceinline__ void mma_bf16(float* c, const uint32_t* a, const uint32_t* b) {
    asm volatile(
        "mma.sync.aligned.m16n8k16.row.col.f32.bf16.bf16.f32 "
        "{%0,%1,%2,%3}, {%4,%5,%6,%7}, {%8,%9}, {%0,%1,%2,%3};"
        : "+f"(c[0]), "+f"(c[1]), "+f"(c[2]), "+f"(c[3])
        : "r"(a[0]), "r"(a[1]), "r"(a[2]), "r"(a[3]), "r"(b[0]), "r"(b[1]));
}

// fp32 -> (hi, lo) bf16 split
__device__ __forceinline__ void store_split4(__nv_bfloat16* __restrict__ hb,
                                             __nv_bfloat16* __restrict__ lb,
                                             size_t base, float4 v) {
    __nv_bfloat16 h0 = __float2bfloat16(v.x), h1 = __float2bfloat16(v.y);
    __nv_bfloat16 h2 = __float2bfloat16(v.z), h3 = __float2bfloat16(v.w);
    __nv_bfloat16 l0 = __float2bfloat16(v.x - __bfloat162float(h0));
    __nv_bfloat16 l1 = __float2bfloat16(v.y - __bfloat162float(h1));
    __nv_bfloat16 l2 = __float2bfloat16(v.z - __bfloat162float(h2));
    __nv_bfloat16 l3 = __float2bfloat16(v.w - __bfloat162float(h3));
    __nv_bfloat162 H0; H0.x = h0; H0.y = h1;
    __nv_bfloat162 H1; H1.x = h2; H1.y = h3;
    __nv_bfloat162 L0; L0.x = l0; L0.y = l1;
    __nv_bfloat162 L1; L1.x = l2; L1.y = l3;
    *reinterpret_cast<__nv_bfloat162*>(hb + base)     = H0;
    *reinterpret_cast<__nv_bfloat162*>(hb + base + 2) = H1;
    *reinterpret_cast<__nv_bfloat162*>(lb + base)     = L0;
    *reinterpret_cast<__nv_bfloat162*>(lb + base + 2) = L1;
}

// ---------------------------------------------------------------------------
// Kernel: generic fp32 -> split bf16 (weights)
// ---------------------------------------------------------------------------
__global__ void split_kernel(const float4* __restrict__ src,
                             __nv_bfloat16* __restrict__ dh,
                             __nv_bfloat16* __restrict__ dl, int n4) {
    int i = blockIdx.x * blockDim.x + threadIdx.x;
    if (i >= n4) return;
    store_split4(dh, dl, (size_t)i * 4, src[i]);
}

// ---------------------------------------------------------------------------
// Kernel: time-shift mixing fused with bf16 split
// ---------------------------------------------------------------------------
__global__ void mix_split_kernel(const float4* __restrict__ x4,
                                 const float4* __restrict__ tmk4,
                                 const float4* __restrict__ tmv4,
                                 const float4* __restrict__ tmr4) {
    const int C4 = CC / 4;
    int i = blockIdx.x * blockDim.x + threadIdx.x;
    if (i >= NELEM / 4) return;
    int c4 = i % C4;
    int t = (i / C4) % TT;

    float4 xc = x4[i];
    float4 xs = make_float4(0.f, 0.f, 0.f, 0.f);
    if (t > 0) xs = x4[i - C4];

    float4 mk = tmk4[c4], mv = tmv4[c4], mr = tmr4[c4];
    float4 ok, ov, orr;
    ok.x  = xc.x * mk.x + xs.x * (1.f - mk.x);
    ok.y  = xc.y * mk.y + xs.y * (1.f - mk.y);
    ok.z  = xc.z * mk.z + xs.z * (1.f - mk.z);
    ok.w  = xc.w * mk.w + xs.w * (1.f - mk.w);
    ov.x  = xc.x * mv.x + xs.x * (1.f - mv.x);
    ov.y  = xc.y * mv.y + xs.y * (1.f - mv.y);
    ov.z  = xc.z * mv.z + xs.z * (1.f - mv.z);
    ov.w  = xc.w * mv.w + xs.w * (1.f - mv.w);
    orr.x = xc.x * mr.x + xs.x * (1.f - mr.x);
    orr.y = xc.y * mr.y + xs.y * (1.f - mr.y);
    orr.z = xc.z * mr.z + xs.z * (1.f - mr.z);
    orr.w = xc.w * mr.w + xs.w * (1.f - mr.w);

    size_t base = (size_t)i * 4;
    store_split4(g_xkh, g_xkl, base, ok);
    store_split4(g_xvh, g_xvl, base, ov);
    store_split4(g_xrh, g_xrl, base, orr);
}

// ---------------------------------------------------------------------------
// Kernel: split-bf16 HMMA GEMM.
// C[M, N] = (Ah+Al)[M,K] . (Bh+Bl)[N,K]^T ~= AhBh + AhBl + AlBh, fp32 accum.
// 128x128 tile, BK=32, cp.async double-buffer, ldmatrix + mma.sync bf16.
// ---------------------------------------------------------------------------
__global__ __launch_bounds__(256)
void gemm_hmma(const __nv_bfloat16* __restrict__ Ah,
               const __nv_bfloat16* __restrict__ Al,
               const __nv_bfloat16* __restrict__ Bh,
               const __nv_bfloat16* __restrict__ Bl,
               float* __restrict__ C) {
    extern __shared__ __align__(128) char smem[];
    const uint32_t sb = smem_u32(smem);
    const int tid = threadIdx.x;
    const int wid = tid >> 5;
    const int lane = tid & 31;
    const int wm = wid >> 2;          // 0..1  (64-row half)
    const int wn = wid & 3;           // 0..3  (32-col quarter)
    const int rowBase = blockIdx.y * BM;
    const int colBase = blockIdx.x * BN;
    const int warpRow = wm * 64;
    const int warpCol = wn * 32;

    // Tile base offsets within a stage
    const uint32_t OF_AH = 0, OF_AL = TILEB, OF_BH = 2 * TILEB, OF_BL = 3 * TILEB;

    // cp.async load mapping: 512 x 16B per tile; thread does idx = tid + it*256
    // r = idx>>2 (row 0..127), c = idx&3 (16B chunk)
    auto issue_stage = [&](int buf, int k0) {
        uint32_t sbase = sb + buf * STAGEB;
#pragma unroll
        for (int it = 0; it < 2; it++) {
            int idx = tid + it * 256;
            int r = idx >> 2, c = idx & 3;
            uint32_t so = (uint32_t)(r * SROWB + c * 16);
            size_t gA = (size_t)(rowBase + r) * CC + k0 + c * 8;
            size_t gB = (size_t)(colBase + r) * CC + k0 + c * 8;
            cp_async16(sbase + OF_AH + so, Ah + gA);
            cp_async16(sbase + OF_AL + so, Al + gA);
            cp_async16(sbase + OF_BH + so, Bh + gB);
            cp_async16(sbase + OF_BL + so, Bl + gB);
        }
        cp_commit();
    };

    float acc[4][4][4];
#pragma unroll
    for (int i = 0; i < 4; i++)
#pragma unroll
        for (int j = 0; j < 4; j++)
#pragma unroll
            for (int q = 0; q < 4; q++) acc[i][j][q] = 0.f;

    // ldmatrix per-lane base offsets
    // A (m16k16 atoms): lane -> row = lane&15, k-half = lane>>4
    const uint32_t aLaneOff =
        (uint32_t)((warpRow + (lane & 15)) * SROWB + (lane >> 4) * 8 * 2);
    // B (two n8k16 atoms per x4): g = lane>>3
    const int bg = lane >> 3, bw = lane & 7;
    const uint32_t bLaneOff =
        (uint32_t)((warpCol + (bg >> 1) * 8 + bw) * SROWB + (bg & 1) * 8 * 2);

    issue_stage(0, 0);

#pragma unroll 1
    for (int j = 0; j < NITER; j++) {
        const int buf = j & 1;
        if (j + 1 < NITER) {
            issue_stage(buf ^ 1, (j + 1) * BKK);
            cp_wait1();
        } else {
            cp_wait0();
        }
        __syncthreads();

        const uint32_t sbase = sb + buf * STAGEB;
#pragma unroll
        for (int kk = 0; kk < 2; kk++) {
            const uint32_t kOff = kk * 16 * 2;  // 16 bf16 = 32 bytes
            uint32_t ah[4][4], al[4][4], bh[4][2], bl[4][2];
#pragma unroll
            for (int i = 0; i < 4; i++) {
                uint32_t ad = sbase + OF_AH + aLaneOff + i * 16 * SROWB + kOff;
                ldsm_x4(ad, ah[i][0], ah[i][1], ah[i][2], ah[i][3]);
                uint32_t ad2 = sbase + OF_AL + aLaneOff + i * 16 * SROWB + kOff;
                ldsm_x4(ad2, al[i][0], al[i][1], al[i][2], al[i][3]);
            }
#pragma unroll
            for (int jp = 0; jp < 2; jp++) {
                uint32_t bd = sbase + OF_BH + bLaneOff + jp * 16 * SROWB + kOff;
                ldsm_x4(bd, bh[jp * 2][0], bh[jp * 2][1], bh[jp * 2 + 1][0],
                        bh[jp * 2 + 1][1]);
                uint32_t bd2 = sbase + OF_BL + bLaneOff + jp * 16 * SROWB + kOff;
                ldsm_x4(bd2, bl[jp * 2][0], bl[jp * 2][1], bl[jp * 2 + 1][0],
                        bl[jp * 2 + 1][1]);
            }
#pragma unroll
            for (int i = 0; i < 4; i++)
#pragma unroll
                for (int jj = 0; jj < 4; jj++) {
                    mma_bf16(acc[i][jj], ah[i], bh[jj]);
                    mma_bf16(acc[i][jj], ah[i], bl[jj]);
                    mma_bf16(acc[i][jj], al[i], bh[jj]);
                }
        }
        __syncthreads();
    }

    // Epilogue: c0,c1 -> (row r, col 2c..2c+1), c2,c3 -> (row r+8)
    const int er = lane >> 2, ec = (lane & 3) * 2;
#pragma unroll
    for (int i = 0; i < 4; i++) {
#pragma unroll
        for (int jj = 0; jj < 4; jj++) {
            size_t row0 = (size_t)(rowBase + warpRow + i * 16 + er);
            size_t col = (size_t)(colBase + warpCol + jj * 8 + ec);
            float2 v0 = make_float2(acc[i][jj][0], acc[i][jj][1]);
            float2 v1 = make_float2(acc[i][jj][2], acc[i][jj][3]);
            *reinterpret_cast<float2*>(C + row0 * CC + col) = v0;
            *reinterpret_cast<float2*>(C + (row0 + 8) * CC + col) = v1;
        }
    }
}

// ---------------------------------------------------------------------------
// Kernel: WKV recurrence + sigmoid(r) fusion; outputs split bf16
// ---------------------------------------------------------------------------
__global__ void wkv_kernel(const float* __restrict__ k,
                           const float* __restrict__ v,
                           const float* __restrict__ r,
                           const float* __restrict__ time_decay,
                           const float* __restrict__ time_first,
                           __nv_bfloat16* __restrict__ sh,
                           __nv_bfloat16* __restrict__ sl) {
    int tidg = blockIdx.x * blockDim.x + threadIdx.x;  // 0 .. B*C-1
    if (tidg >= BB * CC) return;
    int b = tidg / CC;
    int c = tidg % CC;

    const float w = -__expf(time_decay[c]);
    const float u = time_first[c];

    float num = 0.f, den = 0.f, mx = -1e38f;
    size_t base = (size_t)b * TT * CC + c;

#pragma unroll 4
    for (int t = 0; t < TT; t++) {
        size_t idx = base + (size_t)t * CC;
        float kt = k[idx];
        float vt = v[idx];
        float rv = r[idx];

        float ku = kt + u;
        float max_out = fmaxf(mx, ku);
        float e1 = __expf(mx - max_out);
        float e2 = __expf(ku - max_out);
        float o = __fdividef(e1 * num + e2 * vt, e1 * den + e2);

        float mw = mx + w;
        float max_st = fmaxf(mw, kt);
        float e1s = __expf(mw - max_st);
        float e2s = __expf(kt - max_st);
        num = e1s * num + e2s * vt;
        den = e1s * den + e2s;
        mx = max_st;

        float sr = __fdividef(1.f, 1.f + __expf(-rv));
        float val = sr * o;
        __nv_bfloat16 h = __float2bfloat16(val);
        sh[idx] = h;
        sl[idx] = __float2bfloat16(val - __bfloat162float(h));
    }
}

// ---------------------------------------------------------------------------
// Launch
// ---------------------------------------------------------------------------
extern "C" void kernel_launch(void* const* d_in, const int* in_sizes, int n_in,
                              void* d_out, int out_size) {
    const float* x   = (const float*)d_in[0];
    const float* td  = (const float*)d_in[1];
    const float* tf  = (const float*)d_in[2];
    const float* tmk = (const float*)d_in[3];
    const float* tmv = (const float*)d_in[4];
    const float* tmr = (const float*)d_in[5];
    const float* Wk  = (const float*)d_in[6];
    const float* Wv  = (const float*)d_in[7];
    const float* Wr  = (const float*)d_in[8];
    const float* Wo  = (const float*)d_in[9];
    float* out = (float*)d_out;

    static bool inited = false;
    static __nv_bfloat16 *p_xkh, *p_xkl, *p_xvh, *p_xvl, *p_xrh, *p_xrl;
    static __nv_bfloat16 *p_wh, *p_wl, *p_sh, *p_sl;
    static float *p_k, *p_v, *p_r;
    if (!inited) {
        cudaGetSymbolAddress((void**)&p_xkh, g_xkh);
        cudaGetSymbolAddress((void**)&p_xkl, g_xkl);
        cudaGetSymbolAddress((void**)&p_xvh, g_xvh);
        cudaGetSymbolAddress((void**)&p_xvl, g_xvl);
        cudaGetSymbolAddress((void**)&p_xrh, g_xrh);
        cudaGetSymbolAddress((void**)&p_xrl, g_xrl);
        cudaGetSymbolAddress((void**)&p_wh,  g_wh);
        cudaGetSymbolAddress((void**)&p_wl,  g_wl);
        cudaGetSymbolAddress((void**)&p_k,   g_k);
        cudaGetSymbolAddress((void**)&p_v,   g_v);
        cudaGetSymbolAddress((void**)&p_r,   g_r);
        cudaGetSymbolAddress((void**)&p_sh,  g_sh);
        cudaGetSymbolAddress((void**)&p_sl,  g_sl);
        cudaFuncSetAttribute(gemm_hmma,
                             cudaFuncAttributeMaxDynamicSharedMemorySize, GSMEM);
        inited = true;
    }

    // 1. split the 4 weight matrices to bf16 hi/lo
    {
        int n4 = CC * CC / 4;
        int blocks = (n4 + 255) / 256;
        split_kernel<<<blocks, 256>>>((const float4*)Wk, p_wh + 0ULL * CC * CC,
                                      p_wl + 0ULL * CC * CC, n4);
        split_kernel<<<blocks, 256>>>((const float4*)Wv, p_wh + 1ULL * CC * CC,
                                      p_wl + 1ULL * CC * CC, n4);
        split_kernel<<<blocks, 256>>>((const float4*)Wr, p_wh + 2ULL * CC * CC,
                                      p_wl + 2ULL * CC * CC, n4);
        split_kernel<<<blocks, 256>>>((const float4*)Wo, p_wh + 3ULL * CC * CC,
                                      p_wl + 3ULL * CC * CC, n4);
    }

    // 2. time-shift mixing + split
    {
        int n4 = NELEM / 4;
        mix_split_kernel<<<(n4 + 255) / 256, 256>>>(
            (const float4*)x, (const float4*)tmk, (const float4*)tmv, (const float4*)tmr);
    }

    // 3. projection GEMMs (HMMA)
    dim3 gg(CC / BN, MM / BM);  // (16, 64)
    gemm_hmma<<<gg, 256, GSMEM>>>(p_xkh, p_xkl, p_wh + 0ULL * CC * CC,
                                  p_wl + 0ULL * CC * CC, p_k);
    gemm_hmma<<<gg, 256, GSMEM>>>(p_xvh, p_xvl, p_wh + 1ULL * CC * CC,
                                  p_wl + 1ULL * CC * CC, p_v);
    gemm_hmma<<<gg, 256, GSMEM>>>(p_xrh, p_xrl, p_wh + 2ULL * CC * CC,
                                  p_wl + 2ULL * CC * CC, p_r);

    // 4. WKV recurrence + sigmoid fusion (outputs split bf16)
    {
        int threads = 128;
        int blocks = (BB * CC + threads - 1) / threads;
        wkv_kernel<<<blocks, threads>>>(p_k, p_v, p_r, td, tf, p_sh, p_sl);
    }

    // 5. output GEMM into d_out
    gemm_hmma<<<gg, 256, GSMEM>>>(p_sh, p_sl, p_wh + 3ULL * CC * CC,
                                  p_wl + 3ULL * CC * CC, out);
}